// round 5
// baseline (speedup 1.0000x reference)
#include <cuda_runtime.h>

#define B_    2048
#define FS_   32
#define FA_   16
#define T_    512
#define H_    64
#define SQRT_DT_ 0.22360679774997896f
#define MIN_V_  (-5.0f)
#define MAX_V_  (5.0f)

typedef unsigned long long u64;

__device__ __forceinline__ u64 pack2(float lo, float hi) {
    u64 r; asm("mov.b64 %0, {%1, %2};" : "=l"(r) : "f"(lo), "f"(hi)); return r;
}
__device__ __forceinline__ float2 unpack2(u64 v) {
    float2 f; asm("mov.b64 {%0, %1}, %2;" : "=f"(f.x), "=f"(f.y) : "l"(v)); return f;
}
// packed dual fp32 FMA (sm_100+)
__device__ __forceinline__ u64 ffma2(u64 a, u64 b, u64 c) {
    u64 d; asm("fma.rn.f32x2 %0, %1, %2, %3;" : "=l"(d) : "l"(a), "l"(b), "l"(c)); return d;
}
// accurate tanh from ex2.approx + rcp.approx (~1e-7 abs err)
__device__ __forceinline__ float tanh_acc(float x) {
    float e, r;
    asm("ex2.approx.f32 %0, %1;" : "=f"(e) : "f"(x * 2.8853900817779268f)); // 2*log2(e)
    asm("rcp.approx.f32 %0, %1;" : "=f"(r) : "f"(e + 1.0f));
    return (e - 1.0f) * r;
}

// Block = 256 threads = 8 warps = 4 (f,g) pairs; 4 batch elements per pair,
// 16 per block, grid = 128 (single wave). Only w1a (48 regs) stays register-
// resident; w1b and w2 stream from SMEM (per-lane LDS.128, reused across the
// 4 elements) so ~110 registers are freed for operand run-ahead. One named
// barrier per step; both warps redundantly finalize x into private buffers.
__global__ void __launch_bounds__(256, 1)
sde_kernel(const float* __restrict__ a_in,   // (B, FA, T)
           const float* __restrict__ x0,     // (B, FS)
           const float* __restrict__ noise,  // (T-1, B, FS)
           const float* __restrict__ Wf1, const float* __restrict__ bf1,
           const float* __restrict__ Wf2, const float* __restrict__ bf2,
           const float* __restrict__ Wg1, const float* __restrict__ bg1,
           const float* __restrict__ Wg2, const float* __restrict__ bg2,
           float* __restrict__ out)          // (B, FS, T)
{
    const int tid  = threadIdx.x;
    const int wid  = tid >> 5;
    const int lane = tid & 31;
    const int pair = wid >> 1;            // 0..3
    const bool is_g = (wid & 1) != 0;
    const int m    = is_g ? 1 : 0;
    const int el0  = pair * 4;
    const int gb0  = blockIdx.x * 16 + el0;

    __shared__ __align__(16) float v_sm[8][4][64];        // per-warp x/h buffer (8KB)
    __shared__ __align__(16) float a_sg[2][16][4][16];    // a tiles, 4 steps, transposed (8KB)
    __shared__ __align__(16) float ex_sm[2][4][2][4][32]; // {o_f,d} exchange, dbl-buf (8KB)
    __shared__ __align__(16) float4 sW1b[2][12][32];      // W1[:, 32+j] pair-packed (12KB)
    __shared__ __align__(16) float4 sW2 [2][16][32];      // W2[:, j] pair-packed (16KB)

    const float* W1 = is_g ? Wg1 : Wf1;
    const float* b1 = is_g ? bg1 : bf1;
    const float* b2 = is_g ? bg2 : bf2;

    // ---- cooperative weight packing into SMEM ----
    // sW1b[mm][G][j] = W1mm[(4G+i)*64 + 32 + j], i=0..3  (pairs 2G, 2G+1)
    for (int idx = tid; idx < 2 * 12 * 32; idx += 256) {
        const int mm = idx / (12 * 32);
        const int G  = (idx / 32) % 12;
        const int j  = idx & 31;
        const float* W = mm ? Wg1 : Wf1;
        sW1b[mm][G][j] = make_float4(W[(4*G+0)*H_ + 32 + j], W[(4*G+1)*H_ + 32 + j],
                                     W[(4*G+2)*H_ + 32 + j], W[(4*G+3)*H_ + 32 + j]);
    }
    // sW2[mm][q][j] = W2mm[(4q+i)*32 + j]
    for (int idx = tid; idx < 2 * 16 * 32; idx += 256) {
        const int mm = idx / (16 * 32);
        const int q  = (idx / 32) % 16;
        const int j  = idx & 31;
        const float* W = mm ? Wg2 : Wf2;
        sW2[mm][q][j] = make_float4(W[(4*q+0)*FS_ + j], W[(4*q+1)*FS_ + j],
                                    W[(4*q+2)*FS_ + j], W[(4*q+3)*FS_ + j]);
    }

    // ---- register-resident w1a only (24 u64 = 48 regs) ----
    u64 w1a[24];
#pragma unroll
    for (int kp = 0; kp < 24; kp++)
        w1a[kp] = pack2(W1[(2*kp)*H_ + lane], W1[(2*kp+1)*H_ + lane]);

    const float bias1a = b1[lane];
    const float bias1b = b1[lane + 32];
    const float bias2  = b2[lane];

    const float* a_base  = a_in  + (size_t)gb0 * (FA_*T_) + (size_t)(lane >> 1) * T_ + (lane & 1) * 2;
    const float* nz_base = noise + (size_t)gb0 * FS_ + lane;
    float*       out_b   = out   + (size_t)gb0 * (FS_*T_) + (size_t)lane * T_;

    float2 areg[4];
    float  eps_n[4];

    // -------- prologue --------
#pragma unroll
    for (int e = 0; e < 4; e++) {
        float xv = x0[(size_t)(gb0 + e) * FS_ + lane];
        v_sm[wid][e][lane] = xv;
        if (!is_g) out_b[(size_t)e * (FS_*T_)] = xv;
    }
    if (!is_g) {
#pragma unroll
        for (int e = 0; e < 4; e++) {
            float2 v = *reinterpret_cast<const float2*>(a_base + (size_t)e * (FA_*T_));
            a_sg[0][el0 + e][(lane & 1)*2 + 0][lane >> 1] = v.x;
            a_sg[0][el0 + e][(lane & 1)*2 + 1][lane >> 1] = v.y;
        }
#pragma unroll
        for (int e = 0; e < 4; e++)
            areg[e] = *reinterpret_cast<const float2*>(a_base + (size_t)e * (FA_*T_) + 4);
    } else {
#pragma unroll
        for (int e = 0; e < 4; e++) eps_n[e] = nz_base[e * FS_];
    }
    __syncthreads();

    const int bar_id = 1 + pair;

#pragma unroll 1
    for (int t = 1; t < T_; t++) {
        const int ai  = t - 1;
        const int tb  = t & 1;
        const int g4  = ai >> 2;
        const int buf = g4 & 1;
        const int sl  = ai & 3;

        // g: rotate noise double-buffer; issue next load early
        float eps_u[4];
        if (is_g) {
#pragma unroll
            for (int e = 0; e < 4; e++) eps_u[e] = eps_n[e];
            if (t < T_ - 1) {
                const float* np = nz_base + (size_t)t * (B_ * FS_);
#pragma unroll
                for (int e = 0; e < 4; e++) eps_n[e] = np[e * FS_];
            }
        }

        // ---------------- layer 1 (48 -> 64), 8 chains ----------------
        u64 aa[4], ab[4];
#pragma unroll
        for (int e = 0; e < 4; e++) { aa[e] = 0ull; ab[e] = 0ull; }

        // a-part: groups 0..3 (pairs 0..7, s[0:16) = a_t)
#pragma unroll
        for (int q = 0; q < 4; q++) {
            float4 wb = sW1b[m][q][lane];
            const u64 wb0 = pack2(wb.x, wb.y), wb1 = pack2(wb.z, wb.w);
            const u64 wA0 = w1a[2*q], wA1 = w1a[2*q+1];
#pragma unroll
            for (int e = 0; e < 4; e++) {
                ulonglong2 v = *reinterpret_cast<const ulonglong2*>(&a_sg[buf][el0+e][sl][4*q]);
                aa[e] = ffma2(v.x, wA0, aa[e]);
                aa[e] = ffma2(v.y, wA1, aa[e]);
                ab[e] = ffma2(v.x, wb0, ab[e]);
                ab[e] = ffma2(v.y, wb1, ab[e]);
            }
        }
        // x-part: groups 4..11 (pairs 8..23, s[16:48) = x_t)
#pragma unroll
        for (int q = 0; q < 8; q++) {
            float4 wb = sW1b[m][4 + q][lane];
            const u64 wb0 = pack2(wb.x, wb.y), wb1 = pack2(wb.z, wb.w);
            const u64 wA0 = w1a[8+2*q], wA1 = w1a[9+2*q];
#pragma unroll
            for (int e = 0; e < 4; e++) {
                ulonglong2 v = *reinterpret_cast<const ulonglong2*>(&v_sm[wid][e][4*q]);
                aa[e] = ffma2(v.x, wA0, aa[e]);
                aa[e] = ffma2(v.y, wA1, aa[e]);
                ab[e] = ffma2(v.x, wb0, ab[e]);
                ab[e] = ffma2(v.y, wb1, ab[e]);
            }
        }
        // tanh + stash h in private buffer (overwrites x)
#pragma unroll
        for (int e = 0; e < 4; e++) {
            float2 u = unpack2(aa[e]);
            float2 v = unpack2(ab[e]);
            v_sm[wid][e][lane]      = tanh_acc(u.x + u.y + bias1a);
            v_sm[wid][e][lane + 32] = tanh_acc(v.x + v.y + bias1b);
        }
        __syncwarp();

        // ---------------- layer 2 (64 -> 32), 8 chains ----------------
        u64 c0[4], c1[4];
#pragma unroll
        for (int e = 0; e < 4; e++) { c0[e] = 0ull; c1[e] = 0ull; }
#pragma unroll
        for (int q = 0; q < 16; q++) {
            float4 wf = sW2[m][q][lane];
            const u64 w0 = pack2(wf.x, wf.y), w1x = pack2(wf.z, wf.w);
#pragma unroll
            for (int e = 0; e < 4; e++) {
                ulonglong2 v = *reinterpret_cast<const ulonglong2*>(&v_sm[wid][e][4*q]);
                c0[e] = ffma2(v.x, w0,  c0[e]);
                c1[e] = ffma2(v.y, w1x, c1[e]);
            }
        }
        float o[4];
#pragma unroll
        for (int e = 0; e < 4; e++) {
            float2 u0 = unpack2(c0[e]), u1 = unpack2(c1[e]);
            o[e] = (u0.x + u0.y) + (u1.x + u1.y) + bias2;
        }

        // publish: f -> o_f (incl. bias), g -> full diffusion term d
        if (!is_g) {
#pragma unroll
            for (int e = 0; e < 4; e++) ex_sm[tb][pair][0][e][lane] = o[e];
        } else {
#pragma unroll
            for (int e = 0; e < 4; e++) ex_sm[tb][pair][1][e][lane] = o[e] * (eps_u[e] * SQRT_DT_);
        }

        // f: a-tile staging pre-barrier (fills partner-wait window)
        if (!is_g) {
            if (sl == 2 && g4 + 1 < 128) {
#pragma unroll
                for (int e = 0; e < 4; e++) {
                    a_sg[buf ^ 1][el0 + e][(lane & 1)*2 + 0][lane >> 1] = areg[e].x;
                    a_sg[buf ^ 1][el0 + e][(lane & 1)*2 + 1][lane >> 1] = areg[e].y;
                }
            }
            if (sl == 3 && g4 + 2 < 128) {
                const float* ap = a_base + (size_t)(g4 + 2) * 4;
#pragma unroll
                for (int e = 0; e < 4; e++)
                    areg[e] = *reinterpret_cast<const float2*>(ap + (size_t)e * (FA_*T_));
            }
        }

        asm volatile("bar.sync %0, 64;" :: "r"(bar_id) : "memory");

        // both warps redundantly finalize x into their own buffer
#pragma unroll
        for (int e = 0; e < 4; e++) {
            float xv = ex_sm[tb][pair][0][e][lane] + ex_sm[tb][pair][1][e][lane];
            xv = fminf(fmaxf(xv, MIN_V_), MAX_V_);
            v_sm[wid][e][lane] = xv;                  // overwrite h with new x
            if (!is_g) out_b[(size_t)e * (FS_*T_) + t] = xv;
        }
        __syncwarp();
    }
}

extern "C" void kernel_launch(void* const* d_in, const int* in_sizes, int n_in,
                              void* d_out, int out_size) {
    (void)in_sizes; (void)n_in; (void)out_size;
    // metadata order: ts, in_signal, x0, noise, Wf1, bf1, Wf2, bf2, Wg1, bg1, Wg2, bg2
    const float* a_in  = (const float*)d_in[1];
    const float* x0    = (const float*)d_in[2];
    const float* noise = (const float*)d_in[3];
    const float* Wf1   = (const float*)d_in[4];
    const float* bf1   = (const float*)d_in[5];
    const float* Wf2   = (const float*)d_in[6];
    const float* bf2   = (const float*)d_in[7];
    const float* Wg1   = (const float*)d_in[8];
    const float* bg1   = (const float*)d_in[9];
    const float* Wg2   = (const float*)d_in[10];
    const float* bg2   = (const float*)d_in[11];
    float* out = (float*)d_out;

    sde_kernel<<<B_ / 16, 256>>>(a_in, x0, noise,
                                 Wf1, bf1, Wf2, bf2,
                                 Wg1, bg1, Wg2, bg2,
                                 out);
}